// round 1
// baseline (speedup 1.0000x reference)
#include <cuda_runtime.h>
#include <cstdint>

#define BB 4
#define NN 4096
#define NSAMP 1024
#define KNB 32
#define MTOT (BB*NSAMP*KNB)   // 131072 positions

// ---------------- scratch (device globals; no allocations allowed) ------------
__device__ float g_w21[256*6];
__device__ int   g_knn[BB*NSAMP*KNB];
__device__ float g_y1[(size_t)256*MTOT];   // conv1 output pre-BN   (134MB)
__device__ float g_xm[256*BB*NSAMP];       // max over k of BN2-ReLU
__device__ float g_h3[512*BB*NSAMP];       // w3a @ xm
__device__ float g_y3[(size_t)512*MTOT];   // conv3 output pre-BN   (268MB)
__device__ float g_y4[(size_t)256*MTOT];   // conv4 output pre-BN   (134MB)
__device__ float g_sum[512], g_sq[512];
__device__ float g_s2[256], g_t2[256];
__device__ float g_s3[512], g_t3[512];
__device__ float g_s4[256], g_t4[256];

// ---------------- helpers ----------------------------------------------------
__device__ __forceinline__ unsigned long long dup2(float a) {
    unsigned int u = __float_as_uint(a);
    return ((unsigned long long)u << 32) | (unsigned long long)u;
}
__device__ __forceinline__ unsigned int fmono(float f) {
    unsigned int u = __float_as_uint(f);
    return (u & 0x80000000u) ? ~u : (u | 0x80000000u);
}

// ---------------- w21 = w2 @ w1 (256x6), tiny --------------------------------
__global__ void k_w21(const float* __restrict__ w1, const float* __restrict__ w2) {
    int o = threadIdx.x;
    float acc[6] = {0.f,0.f,0.f,0.f,0.f,0.f};
    for (int c = 0; c < 256; ++c) {
        float w = w2[o*256 + c];
        #pragma unroll
        for (int i = 0; i < 6; ++i) acc[i] = fmaf(w, w1[c*6+i], acc[i]);
    }
    #pragma unroll
    for (int i = 0; i < 6; ++i) g_w21[o*6+i] = acc[i];
}

// ---------------- FPS: one block per batch, 1024 thr, 4 pts/thr --------------
__global__ void k_fps(const float* __restrict__ p, float* __restrict__ outC) {
    int b = blockIdx.x;
    const float* pb = p + b*NN*3;
    int t = threadIdx.x;
    float px[4], py[4], pz[4], dm[4];
    #pragma unroll
    for (int j = 0; j < 4; ++j) {
        int i = t + j*1024;
        px[j] = pb[i*3]; py[j] = pb[i*3+1]; pz[j] = pb[i*3+2];
        dm[j] = 1e10f;
    }
    __shared__ float s_c[3];
    __shared__ float s_v[32];
    __shared__ int   s_i[32];
    __shared__ int   s_far;
    int far = 0;
    int lane = t & 31, w = t >> 5;
    for (int it = 0; it < NSAMP; ++it) {
        if (t == 0) {
            float cx = pb[far*3], cy = pb[far*3+1], cz = pb[far*3+2];
            s_c[0] = cx; s_c[1] = cy; s_c[2] = cz;
            float* o = outC + (b*NSAMP + it)*3;
            o[0] = cx; o[1] = cy; o[2] = cz;
        }
        __syncthreads();
        float cx = s_c[0], cy = s_c[1], cz = s_c[2];
        float best = -1.0f; int bi = 0;
        #pragma unroll
        for (int j = 0; j < 4; ++j) {
            float dx = px[j]-cx, dy = py[j]-cy, dz = pz[j]-cz;
            float d  = fmaf(dz, dz, fmaf(dy, dy, dx*dx));
            float nd = fminf(dm[j], d);
            dm[j] = nd;
            if (nd > best) { best = nd; bi = t + j*1024; }
        }
        #pragma unroll
        for (int off = 16; off; off >>= 1) {
            float ov = __shfl_down_sync(0xffffffffu, best, off);
            int   oi = __shfl_down_sync(0xffffffffu, bi,   off);
            if (ov > best || (ov == best && oi < bi)) { best = ov; bi = oi; }
        }
        if (lane == 0) { s_v[w] = best; s_i[w] = bi; }
        __syncthreads();
        if (w == 0) {
            best = s_v[lane]; bi = s_i[lane];
            #pragma unroll
            for (int off = 16; off; off >>= 1) {
                float ov = __shfl_down_sync(0xffffffffu, best, off);
                int   oi = __shfl_down_sync(0xffffffffu, bi,   off);
                if (ov > best || (ov == best && oi < bi)) { best = ov; bi = oi; }
            }
            if (lane == 0) s_far = bi;
        }
        __syncthreads();
        far = s_far;
    }
}

// ---------------- KNN: one block (128 thr) per centroid ----------------------
__global__ void k_knn(const float* __restrict__ p, const float* __restrict__ cent) {
    int cid = blockIdx.x;                 // b*NSAMP + s
    int b = cid >> 10;
    const float* pb = p + b*NN*3;
    int t = threadIdx.x;                  // 128
    float cx = cent[cid*3], cy = cent[cid*3+1], cz = cent[cid*3+2];
    float cn = cx*cx + cy*cy + cz*cz;
    unsigned long long key[32];
    #pragma unroll
    for (int j = 0; j < 32; ++j) {
        int i = j*128 + t;
        float x = pb[i*3], y = pb[i*3+1], z = pb[i*3+2];
        float pn = x*x + y*y + z*z;
        float dot = fmaf(cx, x, fmaf(cy, y, cz*z));
        float d2  = fmaf(-2.0f, dot, cn + pn);
        key[j] = ((unsigned long long)fmono(d2) << 32) | (unsigned int)i;
    }
    __shared__ unsigned long long s_part[4];
    __shared__ unsigned long long s_prev;
    unsigned long long prev = 0ull;
    int w = t >> 5, lane = t & 31;
    for (int r = 0; r < KNB; ++r) {
        unsigned long long best = ~0ull;
        #pragma unroll
        for (int j = 0; j < 32; ++j) {
            unsigned long long k = key[j];
            if (k > prev && k < best) best = k;
        }
        #pragma unroll
        for (int off = 16; off; off >>= 1) {
            unsigned long long o = __shfl_down_sync(0xffffffffu, best, off);
            if (o < best) best = o;
        }
        if (lane == 0) s_part[w] = best;
        __syncthreads();
        if (t == 0) {
            unsigned long long m = s_part[0];
            #pragma unroll
            for (int i = 1; i < 4; ++i) if (s_part[i] < m) m = s_part[i];
            s_prev = m;
            g_knn[cid*KNB + r] = (int)(m & 0xffffffffull);
        }
        __syncthreads();
        prev = s_prev;
    }
}

// ---------------- gather + fused conv(6->256)+bias -> g_y1 -------------------
__global__ void k_gconv1(const float* __restrict__ p, const float* __restrict__ f,
                         const float* __restrict__ b2) {
    __shared__ float sw[256*6];
    __shared__ float sb[256];
    int t = threadIdx.x;
    #pragma unroll
    for (int i = 0; i < 6; ++i) sw[t*6+i] = g_w21[t*6+i];
    sb[t] = b2[t];
    int m = blockIdx.x*256 + t;
    int b = m >> 15;                       // 32768 positions per batch
    int idx = g_knn[m];
    const float* pp = p + b*NN*3 + idx*3;
    const float* ff = f + b*3*NN + idx;
    float v0 = pp[0], v1 = pp[1], v2 = pp[2];
    float v3 = ff[0], v4 = ff[NN], v5 = ff[2*NN];
    __syncthreads();
    #pragma unroll 8
    for (int c = 0; c < 256; ++c) {
        const float* wr = &sw[c*6];
        float a = sb[c];
        a = fmaf(wr[0], v0, a); a = fmaf(wr[1], v1, a); a = fmaf(wr[2], v2, a);
        a = fmaf(wr[3], v3, a); a = fmaf(wr[4], v4, a); a = fmaf(wr[5], v5, a);
        g_y1[(size_t)c*MTOT + m] = a;
    }
}

// ---------------- per-channel sum / sumsq (one block per channel) ------------
template<int W>
__global__ void k_stats() {
    const float* y = (W == 2) ? g_y1 : (W == 3) ? g_y3 : g_y4;
    int c = blockIdx.x;
    const float4* row = (const float4*)(y + (size_t)c*MTOT);
    float s = 0.f, q = 0.f;
    for (int j = threadIdx.x; j < MTOT/4; j += 256) {
        float4 v = row[j];
        s += v.x + v.y + v.z + v.w;
        q = fmaf(v.x, v.x, q); q = fmaf(v.y, v.y, q);
        q = fmaf(v.z, v.z, q); q = fmaf(v.w, v.w, q);
    }
    #pragma unroll
    for (int off = 16; off; off >>= 1) {
        s += __shfl_down_sync(0xffffffffu, s, off);
        q += __shfl_down_sync(0xffffffffu, q, off);
    }
    __shared__ float ss[8], qq[8];
    int w = threadIdx.x >> 5, lane = threadIdx.x & 31;
    if (lane == 0) { ss[w] = s; qq[w] = q; }
    __syncthreads();
    if (threadIdx.x == 0) {
        float S = 0.f, Q = 0.f;
        #pragma unroll
        for (int i = 0; i < 8; ++i) { S += ss[i]; Q += qq[i]; }
        g_sum[c] = S; g_sq[c] = Q;
    }
}

// ---------------- BN params: scale/shift -------------------------------------
template<int STAGE>
__global__ void k_params(const float* __restrict__ g, const float* __restrict__ be) {
    constexpr int C = (STAGE == 3) ? 512 : 256;
    float* sc = (STAGE == 2) ? g_s2 : (STAGE == 3) ? g_s3 : g_s4;
    float* sh = (STAGE == 2) ? g_t2 : (STAGE == 3) ? g_t3 : g_t4;
    int c = blockIdx.x*blockDim.x + threadIdx.x;
    if (c < C) {
        const float inv = 1.0f / (float)MTOT;
        float mean = g_sum[c]*inv;
        float var  = fmaf(-mean, mean, g_sq[c]*inv);
        float r    = rsqrtf(var + 1e-5f);
        float s    = g[c]*r;
        sc[c] = s;
        sh[c] = fmaf(-mean, s, be[c]);
    }
}

// ---------------- xm = max_k relu(affine2(y1)) -------------------------------
__global__ void k_xm() {
    int gid = blockIdx.x*256 + threadIdx.x;   // 256*4096 threads
    int c = gid >> 12, bs = gid & 4095;
    float s = g_s2[c], h = g_t2[c];
    const float4* r = (const float4*)(g_y1 + (size_t)c*MTOT + bs*KNB);
    float mx = 0.f;
    #pragma unroll
    for (int j = 0; j < 8; ++j) {
        float4 v = r[j];
        mx = fmaxf(mx, fmaf(v.x, s, h)); mx = fmaxf(mx, fmaf(v.y, s, h));
        mx = fmaxf(mx, fmaf(v.z, s, h)); mx = fmaxf(mx, fmaf(v.w, s, h));
    }
    g_xm[c*(BB*NSAMP) + bs] = mx;
}

// ---------------- fp32 GEMM (FFMA2), 128x128x16 tiles, 8x8/thread ------------
// MODE 0: h3   = w3[:, :256]  @ xm                       (Nn=4096,   Kd=256)
// MODE 1: y3   = w3[:, 256:]  @ relu(aff2(y1)) + h3      (Nn=131072, Kd=256)
// MODE 2: y4   = w4           @ relu(aff3(y3))           (Nn=131072, Kd=512)
template<int MODE>
__global__ void __launch_bounds__(256, 2) k_gemm(const float* __restrict__ A) {
    constexpr int Nn  = (MODE == 0) ? (BB*NSAMP) : MTOT;
    constexpr int Kd  = (MODE == 2) ? 512 : 256;
    constexpr int lda = 512;
    const float* __restrict__ Bm = (MODE == 0) ? g_xm : (MODE == 1) ? g_y1 : g_y3;
    float* __restrict__ C        = (MODE == 0) ? g_h3 : (MODE == 1) ? g_y3 : g_y4;
    const float* __restrict__ bsc = (MODE == 1) ? g_s2 : g_s3;
    const float* __restrict__ bsh = (MODE == 1) ? g_t2 : g_t3;

    __shared__ unsigned long long As[16][128];   // A value duplicated into both f32x2 halves
    __shared__ float Bs[16][128];

    int m0 = blockIdx.x * 128;
    int n0 = blockIdx.y * 128;
    int t  = threadIdx.x;
    int ar  = t & 127, akq = (t >> 7) * 8;       // A: 128 rows x 16 k, 8 floats/thread
    int bkr = t >> 4,  bnc = (t & 15) * 8;       // B: 16 k x 128 n, 8 floats/thread
    int ty = t >> 4, tx = t & 15;                // output 8x8 tile

    unsigned long long acc[8][4];
    #pragma unroll
    for (int i = 0; i < 8; ++i)
        #pragma unroll
        for (int j = 0; j < 4; ++j) acc[i][j] = 0ull;

    for (int k0 = 0; k0 < Kd; k0 += 16) {
        const float* ga = A + (size_t)(m0 + ar)*lda + k0 + akq;
        float4 a0 = *(const float4*)ga;
        float4 a1 = *(const float4*)(ga + 4);
        const float* gb = Bm + (size_t)(k0 + bkr)*Nn + n0 + bnc;
        float4 b0 = *(const float4*)gb;
        float4 b1 = *(const float4*)(gb + 4);
        if (MODE != 0) {
            float s = bsc[k0 + bkr], h = bsh[k0 + bkr];
            b0.x = fmaxf(fmaf(b0.x, s, h), 0.f); b0.y = fmaxf(fmaf(b0.y, s, h), 0.f);
            b0.z = fmaxf(fmaf(b0.z, s, h), 0.f); b0.w = fmaxf(fmaf(b0.w, s, h), 0.f);
            b1.x = fmaxf(fmaf(b1.x, s, h), 0.f); b1.y = fmaxf(fmaf(b1.y, s, h), 0.f);
            b1.z = fmaxf(fmaf(b1.z, s, h), 0.f); b1.w = fmaxf(fmaf(b1.w, s, h), 0.f);
        }
        __syncthreads();
        As[akq+0][ar] = dup2(a0.x); As[akq+1][ar] = dup2(a0.y);
        As[akq+2][ar] = dup2(a0.z); As[akq+3][ar] = dup2(a0.w);
        As[akq+4][ar] = dup2(a1.x); As[akq+5][ar] = dup2(a1.y);
        As[akq+6][ar] = dup2(a1.z); As[akq+7][ar] = dup2(a1.w);
        *(float4*)&Bs[bkr][bnc]     = b0;
        *(float4*)&Bs[bkr][bnc + 4] = b1;
        __syncthreads();
        #pragma unroll
        for (int kk = 0; kk < 16; ++kk) {
            unsigned long long af[8], bf[4];
            const unsigned long long* ap = &As[kk][ty*8];
            #pragma unroll
            for (int i = 0; i < 8; ++i) af[i] = ap[i];
            const unsigned long long* bp = (const unsigned long long*)&Bs[kk][tx*8];
            #pragma unroll
            for (int j = 0; j < 4; ++j) bf[j] = bp[j];
            #pragma unroll
            for (int i = 0; i < 8; ++i)
                #pragma unroll
                for (int j = 0; j < 4; ++j)
                    asm("fma.rn.f32x2 %0, %1, %2, %0;"
                        : "+l"(acc[i][j]) : "l"(af[i]), "l"(bf[j]));
        }
    }

    constexpr int ng5 = Nn >> 5;
    #pragma unroll
    for (int i = 0; i < 8; ++i) {
        int gr = m0 + ty*8 + i;
        float out[8];
        #pragma unroll
        for (int j = 0; j < 4; ++j) {
            out[2*j]   = __uint_as_float((unsigned int)(acc[i][j] & 0xffffffffull));
            out[2*j+1] = __uint_as_float((unsigned int)(acc[i][j] >> 32));
        }
        if (MODE == 1) {
            #pragma unroll
            for (int j = 0; j < 8; ++j)
                out[j] += g_h3[(size_t)gr*ng5 + ((n0 + tx*8 + j) >> 5)];
        }
        float4* cp = (float4*)(C + (size_t)gr*Nn + n0 + tx*8);
        cp[0] = make_float4(out[0], out[1], out[2], out[3]);
        cp[1] = make_float4(out[4], out[5], out[6], out[7]);
    }
}

// ---------------- final: out_feat = max_k relu(affine4(y4)) ------------------
__global__ void k_final(float* __restrict__ out) {
    int gid = blockIdx.x*256 + threadIdx.x;   // 256*4096
    int c = gid >> 12, bs = gid & 4095;
    int b = bs >> 10, s = bs & 1023;
    float sc = g_s4[c], h = g_t4[c];
    const float4* r = (const float4*)(g_y4 + (size_t)c*MTOT + bs*KNB);
    float mx = 0.f;
    #pragma unroll
    for (int j = 0; j < 8; ++j) {
        float4 v = r[j];
        mx = fmaxf(mx, fmaf(v.x, sc, h)); mx = fmaxf(mx, fmaf(v.y, sc, h));
        mx = fmaxf(mx, fmaf(v.z, sc, h)); mx = fmaxf(mx, fmaf(v.w, sc, h));
    }
    out[(((b << 8) + c) << 10) + s] = mx;
}

// ---------------- launcher ---------------------------------------------------
extern "C" void kernel_launch(void* const* d_in, const int* in_sizes, int n_in,
                              void* d_out, int out_size) {
    const float* p   = (const float*)d_in[0];
    const float* f   = (const float*)d_in[1];
    const float* w1  = (const float*)d_in[2];
    const float* w2  = (const float*)d_in[3];
    const float* b2  = (const float*)d_in[4];
    const float* g2  = (const float*)d_in[5];
    const float* be2 = (const float*)d_in[6];
    const float* w3  = (const float*)d_in[7];
    const float* g3  = (const float*)d_in[8];
    const float* be3 = (const float*)d_in[9];
    const float* w4  = (const float*)d_in[10];
    const float* g4  = (const float*)d_in[11];
    const float* be4 = (const float*)d_in[12];
    float* out = (float*)d_out;

    k_w21<<<1, 256>>>(w1, w2);
    k_fps<<<BB, 1024>>>(p, out);                      // writes cntrd into d_out[0..12288)
    k_knn<<<BB*NSAMP, 128>>>(p, out);
    k_gconv1<<<MTOT/256, 256>>>(p, f, b2);
    k_stats<2><<<256, 256>>>();
    k_params<2><<<2, 256>>>(g2, be2);
    k_xm<<<4096, 256>>>();
    k_gemm<0><<<dim3(4, (BB*NSAMP)/128), 256>>>(w3);        // h3 = w3a @ xm
    k_gemm<1><<<dim3(4, MTOT/128), 256>>>(w3 + 256);        // y3 = w3b @ x + h3
    k_stats<3><<<512, 256>>>();
    k_params<3><<<2, 256>>>(g3, be3);
    k_gemm<2><<<dim3(2, MTOT/128), 256>>>(w4);              // y4 = w4 @ x3
    k_stats<4><<<256, 256>>>();
    k_params<4><<<2, 256>>>(g4, be4);
    k_final<<<4096, 256>>>(out + BB*NSAMP*3);
}

// round 2
// speedup vs baseline: 1.0002x; 1.0002x over previous
#include <cuda_runtime.h>
#include <cstdint>

#define BB 4
#define NN 4096
#define NSAMP 1024
#define KNB 32
#define MTOT (BB*NSAMP*KNB)   // 131072 positions

// ---------------- scratch (device globals; no allocations allowed) ------------
__device__ float g_w21[256*6];
__device__ int   g_knn[BB*NSAMP*KNB];
__device__ float g_y1[(size_t)256*MTOT];   // conv1 output pre-BN   (134MB)
__device__ float g_xm[256*BB*NSAMP];       // max over k of BN2-ReLU
__device__ float g_h3[512*BB*NSAMP];       // w3a @ xm
__device__ float g_y3[(size_t)512*MTOT];   // conv3 output pre-BN   (268MB)
__device__ float g_y4[(size_t)256*MTOT];   // conv4 output pre-BN   (134MB)
__device__ float g_sum[512], g_sq[512];
__device__ float g_s2[256], g_t2[256];
__device__ float g_s3[512], g_t3[512];
__device__ float g_s4[256], g_t4[256];

// ---------------- helpers ----------------------------------------------------
__device__ __forceinline__ unsigned long long dup2(float a) {
    unsigned int u = __float_as_uint(a);
    return ((unsigned long long)u << 32) | (unsigned long long)u;
}
__device__ __forceinline__ unsigned int fmono(float f) {
    unsigned int u = __float_as_uint(f);
    return (u & 0x80000000u) ? ~u : (u | 0x80000000u);
}

// ---------------- w21 = w2 @ w1 (256x6), tiny --------------------------------
__global__ void k_w21(const float* __restrict__ w1, const float* __restrict__ w2) {
    int o = threadIdx.x;
    float acc[6] = {0.f,0.f,0.f,0.f,0.f,0.f};
    for (int c = 0; c < 256; ++c) {
        float w = w2[o*256 + c];
        #pragma unroll
        for (int i = 0; i < 6; ++i) acc[i] = fmaf(w, w1[c*6+i], acc[i]);
    }
    #pragma unroll
    for (int i = 0; i < 6; ++i) g_w21[o*6+i] = acc[i];
}

// ---------------- FPS: one block per batch, 1024 thr, 4 pts/thr --------------
__global__ void k_fps(const float* __restrict__ p, float* __restrict__ outC) {
    int b = blockIdx.x;
    const float* pb = p + b*NN*3;
    int t = threadIdx.x;
    float px[4], py[4], pz[4], dm[4];
    #pragma unroll
    for (int j = 0; j < 4; ++j) {
        int i = t + j*1024;
        px[j] = pb[i*3]; py[j] = pb[i*3+1]; pz[j] = pb[i*3+2];
        dm[j] = 1e10f;
    }
    __shared__ float s_c[3];
    __shared__ float s_v[32];
    __shared__ int   s_i[32];
    __shared__ int   s_far;
    int far = 0;
    int lane = t & 31, w = t >> 5;
    for (int it = 0; it < NSAMP; ++it) {
        if (t == 0) {
            float cx = pb[far*3], cy = pb[far*3+1], cz = pb[far*3+2];
            s_c[0] = cx; s_c[1] = cy; s_c[2] = cz;
            float* o = outC + (b*NSAMP + it)*3;
            o[0] = cx; o[1] = cy; o[2] = cz;
        }
        __syncthreads();
        float cx = s_c[0], cy = s_c[1], cz = s_c[2];
        float best = -1.0f; int bi = 0;
        #pragma unroll
        for (int j = 0; j < 4; ++j) {
            float dx = px[j]-cx, dy = py[j]-cy, dz = pz[j]-cz;
            float d  = fmaf(dz, dz, fmaf(dy, dy, dx*dx));
            float nd = fminf(dm[j], d);
            dm[j] = nd;
            if (nd > best) { best = nd; bi = t + j*1024; }
        }
        #pragma unroll
        for (int off = 16; off; off >>= 1) {
            float ov = __shfl_down_sync(0xffffffffu, best, off);
            int   oi = __shfl_down_sync(0xffffffffu, bi,   off);
            if (ov > best || (ov == best && oi < bi)) { best = ov; bi = oi; }
        }
        if (lane == 0) { s_v[w] = best; s_i[w] = bi; }
        __syncthreads();
        if (w == 0) {
            best = s_v[lane]; bi = s_i[lane];
            #pragma unroll
            for (int off = 16; off; off >>= 1) {
                float ov = __shfl_down_sync(0xffffffffu, best, off);
                int   oi = __shfl_down_sync(0xffffffffu, bi,   off);
                if (ov > best || (ov == best && oi < bi)) { best = ov; bi = oi; }
            }
            if (lane == 0) s_far = bi;
        }
        __syncthreads();
        far = s_far;
    }
}

// ---------------- KNN: one block (128 thr) per centroid ----------------------
__global__ void k_knn(const float* __restrict__ p, const float* __restrict__ cent) {
    int cid = blockIdx.x;                 // b*NSAMP + s
    int b = cid >> 10;
    const float* pb = p + b*NN*3;
    int t = threadIdx.x;                  // 128
    float cx = cent[cid*3], cy = cent[cid*3+1], cz = cent[cid*3+2];
    float cn = cx*cx + cy*cy + cz*cz;
    unsigned long long key[32];
    #pragma unroll
    for (int j = 0; j < 32; ++j) {
        int i = j*128 + t;
        float x = pb[i*3], y = pb[i*3+1], z = pb[i*3+2];
        float pn = x*x + y*y + z*z;
        float dot = fmaf(cx, x, fmaf(cy, y, cz*z));
        float d2  = fmaf(-2.0f, dot, cn + pn);
        key[j] = ((unsigned long long)fmono(d2) << 32) | (unsigned int)i;
    }
    __shared__ unsigned long long s_part[4];
    __shared__ unsigned long long s_prev;
    unsigned long long prev = 0ull;
    int w = t >> 5, lane = t & 31;
    for (int r = 0; r < KNB; ++r) {
        unsigned long long best = ~0ull;
        #pragma unroll
        for (int j = 0; j < 32; ++j) {
            unsigned long long k = key[j];
            if (k > prev && k < best) best = k;
        }
        #pragma unroll
        for (int off = 16; off; off >>= 1) {
            unsigned long long o = __shfl_down_sync(0xffffffffu, best, off);
            if (o < best) best = o;
        }
        if (lane == 0) s_part[w] = best;
        __syncthreads();
        if (t == 0) {
            unsigned long long m = s_part[0];
            #pragma unroll
            for (int i = 1; i < 4; ++i) if (s_part[i] < m) m = s_part[i];
            s_prev = m;
            g_knn[cid*KNB + r] = (int)(m & 0xffffffffull);
        }
        __syncthreads();
        prev = s_prev;
    }
}

// ---------------- gather + fused conv(6->256)+bias -> g_y1 -------------------
__global__ void k_gconv1(const float* __restrict__ p, const float* __restrict__ f,
                         const float* __restrict__ b2) {
    __shared__ float sw[256*6];
    __shared__ float sb[256];
    int t = threadIdx.x;
    #pragma unroll
    for (int i = 0; i < 6; ++i) sw[t*6+i] = g_w21[t*6+i];
    sb[t] = b2[t];
    int m = blockIdx.x*256 + t;
    int b = m >> 15;                       // 32768 positions per batch
    int idx = g_knn[m];
    const float* pp = p + b*NN*3 + idx*3;
    const float* ff = f + b*3*NN + idx;
    float v0 = pp[0], v1 = pp[1], v2 = pp[2];
    float v3 = ff[0], v4 = ff[NN], v5 = ff[2*NN];
    __syncthreads();
    #pragma unroll 8
    for (int c = 0; c < 256; ++c) {
        const float* wr = &sw[c*6];
        float a = sb[c];
        a = fmaf(wr[0], v0, a); a = fmaf(wr[1], v1, a); a = fmaf(wr[2], v2, a);
        a = fmaf(wr[3], v3, a); a = fmaf(wr[4], v4, a); a = fmaf(wr[5], v5, a);
        g_y1[(size_t)c*MTOT + m] = a;
    }
}

// ---------------- per-channel sum / sumsq (one block per channel) ------------
template<int W>
__global__ void k_stats() {
    const float* y = (W == 2) ? g_y1 : (W == 3) ? g_y3 : g_y4;
    int c = blockIdx.x;
    const float4* row = (const float4*)(y + (size_t)c*MTOT);
    float s = 0.f, q = 0.f;
    for (int j = threadIdx.x; j < MTOT/4; j += 256) {
        float4 v = row[j];
        s += v.x + v.y + v.z + v.w;
        q = fmaf(v.x, v.x, q); q = fmaf(v.y, v.y, q);
        q = fmaf(v.z, v.z, q); q = fmaf(v.w, v.w, q);
    }
    #pragma unroll
    for (int off = 16; off; off >>= 1) {
        s += __shfl_down_sync(0xffffffffu, s, off);
        q += __shfl_down_sync(0xffffffffu, q, off);
    }
    __shared__ float ss[8], qq[8];
    int w = threadIdx.x >> 5, lane = threadIdx.x & 31;
    if (lane == 0) { ss[w] = s; qq[w] = q; }
    __syncthreads();
    if (threadIdx.x == 0) {
        float S = 0.f, Q = 0.f;
        #pragma unroll
        for (int i = 0; i < 8; ++i) { S += ss[i]; Q += qq[i]; }
        g_sum[c] = S; g_sq[c] = Q;
    }
}

// ---------------- BN params: scale/shift -------------------------------------
template<int STAGE>
__global__ void k_params(const float* __restrict__ g, const float* __restrict__ be) {
    constexpr int C = (STAGE == 3) ? 512 : 256;
    float* sc = (STAGE == 2) ? g_s2 : (STAGE == 3) ? g_s3 : g_s4;
    float* sh = (STAGE == 2) ? g_t2 : (STAGE == 3) ? g_t3 : g_t4;
    int c = blockIdx.x*blockDim.x + threadIdx.x;
    if (c < C) {
        const float inv = 1.0f / (float)MTOT;
        float mean = g_sum[c]*inv;
        float var  = fmaf(-mean, mean, g_sq[c]*inv);
        float r    = rsqrtf(var + 1e-5f);
        float s    = g[c]*r;
        sc[c] = s;
        sh[c] = fmaf(-mean, s, be[c]);
    }
}

// ---------------- xm = max_k relu(affine2(y1)) -------------------------------
__global__ void k_xm() {
    int gid = blockIdx.x*256 + threadIdx.x;   // 256*4096 threads
    int c = gid >> 12, bs = gid & 4095;
    float s = g_s2[c], h = g_t2[c];
    const float4* r = (const float4*)(g_y1 + (size_t)c*MTOT + bs*KNB);
    float mx = 0.f;
    #pragma unroll
    for (int j = 0; j < 8; ++j) {
        float4 v = r[j];
        mx = fmaxf(mx, fmaf(v.x, s, h)); mx = fmaxf(mx, fmaf(v.y, s, h));
        mx = fmaxf(mx, fmaf(v.z, s, h)); mx = fmaxf(mx, fmaf(v.w, s, h));
    }
    g_xm[c*(BB*NSAMP) + bs] = mx;
}

// ---------------- fp32 GEMM (FFMA2), 128x128x16 tiles, 8x8/thread ------------
// MODE 0: h3   = w3[:, :256]  @ xm                       (Nn=4096,   Kd=256)
// MODE 1: y3   = w3[:, 256:]  @ relu(aff2(y1)) + h3      (Nn=131072, Kd=256)
// MODE 2: y4   = w4           @ relu(aff3(y3))           (Nn=131072, Kd=512)
template<int MODE>
__global__ void __launch_bounds__(256, 2) k_gemm(const float* __restrict__ A) {
    constexpr int Nn  = (MODE == 0) ? (BB*NSAMP) : MTOT;
    constexpr int Kd  = (MODE == 2) ? 512 : 256;
    constexpr int lda = 512;
    const float* __restrict__ Bm = (MODE == 0) ? g_xm : (MODE == 1) ? g_y1 : g_y3;
    float* __restrict__ C        = (MODE == 0) ? g_h3 : (MODE == 1) ? g_y3 : g_y4;
    const float* __restrict__ bsc = (MODE == 1) ? g_s2 : g_s3;
    const float* __restrict__ bsh = (MODE == 1) ? g_t2 : g_t3;

    __shared__ unsigned long long As[16][128];   // A value duplicated into both f32x2 halves
    __shared__ float Bs[16][128];

    int m0 = blockIdx.x * 128;
    int n0 = blockIdx.y * 128;
    int t  = threadIdx.x;
    int ar  = t & 127, akq = (t >> 7) * 8;       // A: 128 rows x 16 k, 8 floats/thread
    int bkr = t >> 4,  bnc = (t & 15) * 8;       // B: 16 k x 128 n, 8 floats/thread
    int ty = t >> 4, tx = t & 15;                // output 8x8 tile

    unsigned long long acc[8][4];
    #pragma unroll
    for (int i = 0; i < 8; ++i)
        #pragma unroll
        for (int j = 0; j < 4; ++j) acc[i][j] = 0ull;

    for (int k0 = 0; k0 < Kd; k0 += 16) {
        const float* ga = A + (size_t)(m0 + ar)*lda + k0 + akq;
        float4 a0 = *(const float4*)ga;
        float4 a1 = *(const float4*)(ga + 4);
        const float* gb = Bm + (size_t)(k0 + bkr)*Nn + n0 + bnc;
        float4 b0 = *(const float4*)gb;
        float4 b1 = *(const float4*)(gb + 4);
        if (MODE != 0) {
            float s = bsc[k0 + bkr], h = bsh[k0 + bkr];
            b0.x = fmaxf(fmaf(b0.x, s, h), 0.f); b0.y = fmaxf(fmaf(b0.y, s, h), 0.f);
            b0.z = fmaxf(fmaf(b0.z, s, h), 0.f); b0.w = fmaxf(fmaf(b0.w, s, h), 0.f);
            b1.x = fmaxf(fmaf(b1.x, s, h), 0.f); b1.y = fmaxf(fmaf(b1.y, s, h), 0.f);
            b1.z = fmaxf(fmaf(b1.z, s, h), 0.f); b1.w = fmaxf(fmaf(b1.w, s, h), 0.f);
        }
        __syncthreads();
        As[akq+0][ar] = dup2(a0.x); As[akq+1][ar] = dup2(a0.y);
        As[akq+2][ar] = dup2(a0.z); As[akq+3][ar] = dup2(a0.w);
        As[akq+4][ar] = dup2(a1.x); As[akq+5][ar] = dup2(a1.y);
        As[akq+6][ar] = dup2(a1.z); As[akq+7][ar] = dup2(a1.w);
        *(float4*)&Bs[bkr][bnc]     = b0;
        *(float4*)&Bs[bkr][bnc + 4] = b1;
        __syncthreads();
        #pragma unroll
        for (int kk = 0; kk < 16; ++kk) {
            unsigned long long af[8], bf[4];
            const unsigned long long* ap = &As[kk][ty*8];
            #pragma unroll
            for (int i = 0; i < 8; ++i) af[i] = ap[i];
            const unsigned long long* bp = (const unsigned long long*)&Bs[kk][tx*8];
            #pragma unroll
            for (int j = 0; j < 4; ++j) bf[j] = bp[j];
            #pragma unroll
            for (int i = 0; i < 8; ++i)
                #pragma unroll
                for (int j = 0; j < 4; ++j)
                    asm("fma.rn.f32x2 %0, %1, %2, %0;"
                        : "+l"(acc[i][j]) : "l"(af[i]), "l"(bf[j]));
        }
    }

    constexpr int ng5 = Nn >> 5;
    #pragma unroll
    for (int i = 0; i < 8; ++i) {
        int gr = m0 + ty*8 + i;
        float out[8];
        #pragma unroll
        for (int j = 0; j < 4; ++j) {
            out[2*j]   = __uint_as_float((unsigned int)(acc[i][j] & 0xffffffffull));
            out[2*j+1] = __uint_as_float((unsigned int)(acc[i][j] >> 32));
        }
        if (MODE == 1) {
            #pragma unroll
            for (int j = 0; j < 8; ++j)
                out[j] += g_h3[(size_t)gr*ng5 + ((n0 + tx*8 + j) >> 5)];
        }
        float4* cp = (float4*)(C + (size_t)gr*Nn + n0 + tx*8);
        cp[0] = make_float4(out[0], out[1], out[2], out[3]);
        cp[1] = make_float4(out[4], out[5], out[6], out[7]);
    }
}

// ---------------- final: out_feat = max_k relu(affine4(y4)) ------------------
__global__ void k_final(float* __restrict__ out) {
    int gid = blockIdx.x*256 + threadIdx.x;   // 256*4096
    int c = gid >> 12, bs = gid & 4095;
    int b = bs >> 10, s = bs & 1023;
    float sc = g_s4[c], h = g_t4[c];
    const float4* r = (const float4*)(g_y4 + (size_t)c*MTOT + bs*KNB);
    float mx = 0.f;
    #pragma unroll
    for (int j = 0; j < 8; ++j) {
        float4 v = r[j];
        mx = fmaxf(mx, fmaf(v.x, sc, h)); mx = fmaxf(mx, fmaf(v.y, sc, h));
        mx = fmaxf(mx, fmaf(v.z, sc, h)); mx = fmaxf(mx, fmaf(v.w, sc, h));
    }
    out[(((b << 8) + c) << 10) + s] = mx;
}

// ---------------- launcher ---------------------------------------------------
extern "C" void kernel_launch(void* const* d_in, const int* in_sizes, int n_in,
                              void* d_out, int out_size) {
    const float* p   = (const float*)d_in[0];
    const float* f   = (const float*)d_in[1];
    const float* w1  = (const float*)d_in[2];
    const float* w2  = (const float*)d_in[3];
    const float* b2  = (const float*)d_in[4];
    const float* g2  = (const float*)d_in[5];
    const float* be2 = (const float*)d_in[6];
    const float* w3  = (const float*)d_in[7];
    const float* g3  = (const float*)d_in[8];
    const float* be3 = (const float*)d_in[9];
    const float* w4  = (const float*)d_in[10];
    const float* g4  = (const float*)d_in[11];
    const float* be4 = (const float*)d_in[12];
    float* out = (float*)d_out;

    k_w21<<<1, 256>>>(w1, w2);
    k_fps<<<BB, 1024>>>(p, out);                      // writes cntrd into d_out[0..12288)
    k_knn<<<BB*NSAMP, 128>>>(p, out);
    k_gconv1<<<MTOT/256, 256>>>(p, f, b2);
    k_stats<2><<<256, 256>>>();
    k_params<2><<<2, 256>>>(g2, be2);
    k_xm<<<4096, 256>>>();
    k_gemm<0><<<dim3(4, (BB*NSAMP)/128), 256>>>(w3);        // h3 = w3a @ xm
    k_gemm<1><<<dim3(4, MTOT/128), 256>>>(w3 + 256);        // y3 = w3b @ x + h3
    k_stats<3><<<512, 256>>>();
    k_params<3><<<2, 256>>>(g3, be3);
    k_gemm<2><<<dim3(2, MTOT/128), 256>>>(w4);              // y4 = w4 @ x3
    k_stats<4><<<256, 256>>>();
    k_params<4><<<2, 256>>>(g4, be4);
    k_final<<<4096, 256>>>(out + BB*NSAMP*3);
}

// round 3
// speedup vs baseline: 1.0031x; 1.0029x over previous
#include <cuda_runtime.h>
#include <cstdint>

#define BB 4
#define NN 4096
#define NSAMP 1024
#define KNB 32
#define MTOT (BB*NSAMP*KNB)   // 131072 positions

// ---------------- scratch (device globals; no allocations allowed) ------------
__device__ float g_w21[256*6];
__device__ int   g_knn[BB*NSAMP*KNB];
__device__ float g_y1[(size_t)256*MTOT];   // conv1 output pre-BN   (134MB)
__device__ float g_xm[256*BB*NSAMP];       // max over k of BN2-ReLU
__device__ float g_h3[512*BB*NSAMP];       // w3a @ xm
__device__ float g_y3[(size_t)512*MTOT];   // conv3 output pre-BN   (268MB)
__device__ float g_y4[(size_t)256*MTOT];   // conv4 output pre-BN   (134MB)
__device__ float g_sum[512], g_sq[512];
__device__ float g_s2[256], g_t2[256];
__device__ float g_s3[512], g_t3[512];
__device__ float g_s4[256], g_t4[256];

// ---------------- helpers ----------------------------------------------------
__device__ __forceinline__ unsigned long long dup2(float a) {
    unsigned int u = __float_as_uint(a);
    return ((unsigned long long)u << 32) | (unsigned long long)u;
}
__device__ __forceinline__ unsigned int fmono(float f) {
    unsigned int u = __float_as_uint(f);
    return (u & 0x80000000u) ? ~u : (u | 0x80000000u);
}

// ---------------- w21 = w2 @ w1 (256x6), tiny --------------------------------
__global__ void k_w21(const float* __restrict__ w1, const float* __restrict__ w2) {
    int o = threadIdx.x;
    float acc[6] = {0.f,0.f,0.f,0.f,0.f,0.f};
    for (int c = 0; c < 256; ++c) {
        float w = w2[o*256 + c];
        #pragma unroll
        for (int i = 0; i < 6; ++i) acc[i] = fmaf(w, w1[c*6+i], acc[i]);
    }
    #pragma unroll
    for (int i = 0; i < 6; ++i) g_w21[o*6+i] = acc[i];
}

// ---------------- FPS: one block per batch, 1024 thr, 4 pts/thr --------------
__global__ void k_fps(const float* __restrict__ p, float* __restrict__ outC) {
    int b = blockIdx.x;
    const float* pb = p + b*NN*3;
    int t = threadIdx.x;
    float px[4], py[4], pz[4], dm[4];
    #pragma unroll
    for (int j = 0; j < 4; ++j) {
        int i = t + j*1024;
        px[j] = pb[i*3]; py[j] = pb[i*3+1]; pz[j] = pb[i*3+2];
        dm[j] = 1e10f;
    }
    __shared__ float s_c[3];
    __shared__ float s_v[32];
    __shared__ int   s_i[32];
    __shared__ int   s_far;
    int far = 0;
    int lane = t & 31, w = t >> 5;
    for (int it = 0; it < NSAMP; ++it) {
        if (t == 0) {
            float cx = pb[far*3], cy = pb[far*3+1], cz = pb[far*3+2];
            s_c[0] = cx; s_c[1] = cy; s_c[2] = cz;
            float* o = outC + (b*NSAMP + it)*3;
            o[0] = cx; o[1] = cy; o[2] = cz;
        }
        __syncthreads();
        float cx = s_c[0], cy = s_c[1], cz = s_c[2];
        float best = -1.0f; int bi = 0;
        #pragma unroll
        for (int j = 0; j < 4; ++j) {
            float dx = px[j]-cx, dy = py[j]-cy, dz = pz[j]-cz;
            float d  = fmaf(dz, dz, fmaf(dy, dy, dx*dx));
            float nd = fminf(dm[j], d);
            dm[j] = nd;
            if (nd > best) { best = nd; bi = t + j*1024; }
        }
        #pragma unroll
        for (int off = 16; off; off >>= 1) {
            float ov = __shfl_down_sync(0xffffffffu, best, off);
            int   oi = __shfl_down_sync(0xffffffffu, bi,   off);
            if (ov > best || (ov == best && oi < bi)) { best = ov; bi = oi; }
        }
        if (lane == 0) { s_v[w] = best; s_i[w] = bi; }
        __syncthreads();
        if (w == 0) {
            best = s_v[lane]; bi = s_i[lane];
            #pragma unroll
            for (int off = 16; off; off >>= 1) {
                float ov = __shfl_down_sync(0xffffffffu, best, off);
                int   oi = __shfl_down_sync(0xffffffffu, bi,   off);
                if (ov > best || (ov == best && oi < bi)) { best = ov; bi = oi; }
            }
            if (lane == 0) s_far = bi;
        }
        __syncthreads();
        far = s_far;
    }
}

// ---------------- KNN: one block (128 thr) per centroid ----------------------
__global__ void k_knn(const float* __restrict__ p, const float* __restrict__ cent) {
    int cid = blockIdx.x;                 // b*NSAMP + s
    int b = cid >> 10;
    const float* pb = p + b*NN*3;
    int t = threadIdx.x;                  // 128
    float cx = cent[cid*3], cy = cent[cid*3+1], cz = cent[cid*3+2];
    float cn = cx*cx + cy*cy + cz*cz;
    unsigned long long key[32];
    #pragma unroll
    for (int j = 0; j < 32; ++j) {
        int i = j*128 + t;
        float x = pb[i*3], y = pb[i*3+1], z = pb[i*3+2];
        float pn = x*x + y*y + z*z;
        float dot = fmaf(cx, x, fmaf(cy, y, cz*z));
        float d2  = fmaf(-2.0f, dot, cn + pn);
        key[j] = ((unsigned long long)fmono(d2) << 32) | (unsigned int)i;
    }
    __shared__ unsigned long long s_part[4];
    __shared__ unsigned long long s_prev;
    unsigned long long prev = 0ull;
    int w = t >> 5, lane = t & 31;
    for (int r = 0; r < KNB; ++r) {
        unsigned long long best = ~0ull;
        #pragma unroll
        for (int j = 0; j < 32; ++j) {
            unsigned long long k = key[j];
            if (k > prev && k < best) best = k;
        }
        #pragma unroll
        for (int off = 16; off; off >>= 1) {
            unsigned long long o = __shfl_down_sync(0xffffffffu, best, off);
            if (o < best) best = o;
        }
        if (lane == 0) s_part[w] = best;
        __syncthreads();
        if (t == 0) {
            unsigned long long m = s_part[0];
            #pragma unroll
            for (int i = 1; i < 4; ++i) if (s_part[i] < m) m = s_part[i];
            s_prev = m;
            g_knn[cid*KNB + r] = (int)(m & 0xffffffffull);
        }
        __syncthreads();
        prev = s_prev;
    }
}

// ---------------- gather + fused conv(6->256)+bias -> g_y1 -------------------
__global__ void k_gconv1(const float* __restrict__ p, const float* __restrict__ f,
                         const float* __restrict__ b2) {
    __shared__ float sw[256*6];
    __shared__ float sb[256];
    int t = threadIdx.x;
    #pragma unroll
    for (int i = 0; i < 6; ++i) sw[t*6+i] = g_w21[t*6+i];
    sb[t] = b2[t];
    int m = blockIdx.x*256 + t;
    int b = m >> 15;                       // 32768 positions per batch
    int idx = g_knn[m];
    const float* pp = p + b*NN*3 + idx*3;
    const float* ff = f + b*3*NN + idx;
    float v0 = pp[0], v1 = pp[1], v2 = pp[2];
    float v3 = ff[0], v4 = ff[NN], v5 = ff[2*NN];
    __syncthreads();
    #pragma unroll 8
    for (int c = 0; c < 256; ++c) {
        const float* wr = &sw[c*6];
        float a = sb[c];
        a = fmaf(wr[0], v0, a); a = fmaf(wr[1], v1, a); a = fmaf(wr[2], v2, a);
        a = fmaf(wr[3], v3, a); a = fmaf(wr[4], v4, a); a = fmaf(wr[5], v5, a);
        g_y1[(size_t)c*MTOT + m] = a;
    }
}

// ---------------- per-channel sum / sumsq (one block per channel) ------------
template<int W>
__global__ void k_stats() {
    const float* y = (W == 2) ? g_y1 : (W == 3) ? g_y3 : g_y4;
    int c = blockIdx.x;
    const float4* row = (const float4*)(y + (size_t)c*MTOT);
    float s = 0.f, q = 0.f;
    for (int j = threadIdx.x; j < MTOT/4; j += 256) {
        float4 v = row[j];
        s += v.x + v.y + v.z + v.w;
        q = fmaf(v.x, v.x, q); q = fmaf(v.y, v.y, q);
        q = fmaf(v.z, v.z, q); q = fmaf(v.w, v.w, q);
    }
    #pragma unroll
    for (int off = 16; off; off >>= 1) {
        s += __shfl_down_sync(0xffffffffu, s, off);
        q += __shfl_down_sync(0xffffffffu, q, off);
    }
    __shared__ float ss[8], qq[8];
    int w = threadIdx.x >> 5, lane = threadIdx.x & 31;
    if (lane == 0) { ss[w] = s; qq[w] = q; }
    __syncthreads();
    if (threadIdx.x == 0) {
        float S = 0.f, Q = 0.f;
        #pragma unroll
        for (int i = 0; i < 8; ++i) { S += ss[i]; Q += qq[i]; }
        g_sum[c] = S; g_sq[c] = Q;
    }
}

// ---------------- BN params: scale/shift -------------------------------------
template<int STAGE>
__global__ void k_params(const float* __restrict__ g, const float* __restrict__ be) {
    constexpr int C = (STAGE == 3) ? 512 : 256;
    float* sc = (STAGE == 2) ? g_s2 : (STAGE == 3) ? g_s3 : g_s4;
    float* sh = (STAGE == 2) ? g_t2 : (STAGE == 3) ? g_t3 : g_t4;
    int c = blockIdx.x*blockDim.x + threadIdx.x;
    if (c < C) {
        const float inv = 1.0f / (float)MTOT;
        float mean = g_sum[c]*inv;
        float var  = fmaf(-mean, mean, g_sq[c]*inv);
        float r    = rsqrtf(var + 1e-5f);
        float s    = g[c]*r;
        sc[c] = s;
        sh[c] = fmaf(-mean, s, be[c]);
    }
}

// ---------------- xm = max_k relu(affine2(y1)) -------------------------------
__global__ void k_xm() {
    int gid = blockIdx.x*256 + threadIdx.x;   // 256*4096 threads
    int c = gid >> 12, bs = gid & 4095;
    float s = g_s2[c], h = g_t2[c];
    const float4* r = (const float4*)(g_y1 + (size_t)c*MTOT + bs*KNB);
    float mx = 0.f;
    #pragma unroll
    for (int j = 0; j < 8; ++j) {
        float4 v = r[j];
        mx = fmaxf(mx, fmaf(v.x, s, h)); mx = fmaxf(mx, fmaf(v.y, s, h));
        mx = fmaxf(mx, fmaf(v.z, s, h)); mx = fmaxf(mx, fmaf(v.w, s, h));
    }
    g_xm[c*(BB*NSAMP) + bs] = mx;
}

// ---------------- fp32 GEMM (FFMA2), 128x128x16 tiles, 8x8/thread ------------
// MODE 0: h3   = w3[:, :256]  @ xm                       (Nn=4096,   Kd=256)
// MODE 1: y3   = w3[:, 256:]  @ relu(aff2(y1)) + h3      (Nn=131072, Kd=256)
// MODE 2: y4   = w4           @ relu(aff3(y3))           (Nn=131072, Kd=512)
template<int MODE>
__global__ void __launch_bounds__(256, 2) k_gemm(const float* __restrict__ A) {
    constexpr int Nn  = (MODE == 0) ? (BB*NSAMP) : MTOT;
    constexpr int Kd  = (MODE == 2) ? 512 : 256;
    constexpr int lda = 512;
    const float* __restrict__ Bm = (MODE == 0) ? g_xm : (MODE == 1) ? g_y1 : g_y3;
    float* __restrict__ C        = (MODE == 0) ? g_h3 : (MODE == 1) ? g_y3 : g_y4;
    const float* __restrict__ bsc = (MODE == 1) ? g_s2 : g_s3;
    const float* __restrict__ bsh = (MODE == 1) ? g_t2 : g_t3;

    __shared__ unsigned long long As[16][128];   // A value duplicated into both f32x2 halves
    __shared__ float Bs[16][128];

    int m0 = blockIdx.x * 128;
    int n0 = blockIdx.y * 128;
    int t  = threadIdx.x;
    int ar  = t & 127, akq = (t >> 7) * 8;       // A: 128 rows x 16 k, 8 floats/thread
    int bkr = t >> 4,  bnc = (t & 15) * 8;       // B: 16 k x 128 n, 8 floats/thread
    int ty = t >> 4, tx = t & 15;                // output 8x8 tile

    unsigned long long acc[8][4];
    #pragma unroll
    for (int i = 0; i < 8; ++i)
        #pragma unroll
        for (int j = 0; j < 4; ++j) acc[i][j] = 0ull;

    for (int k0 = 0; k0 < Kd; k0 += 16) {
        const float* ga = A + (size_t)(m0 + ar)*lda + k0 + akq;
        float4 a0 = *(const float4*)ga;
        float4 a1 = *(const float4*)(ga + 4);
        const float* gb = Bm + (size_t)(k0 + bkr)*Nn + n0 + bnc;
        float4 b0 = *(const float4*)gb;
        float4 b1 = *(const float4*)(gb + 4);
        if (MODE != 0) {
            float s = bsc[k0 + bkr], h = bsh[k0 + bkr];
            b0.x = fmaxf(fmaf(b0.x, s, h), 0.f); b0.y = fmaxf(fmaf(b0.y, s, h), 0.f);
            b0.z = fmaxf(fmaf(b0.z, s, h), 0.f); b0.w = fmaxf(fmaf(b0.w, s, h), 0.f);
            b1.x = fmaxf(fmaf(b1.x, s, h), 0.f); b1.y = fmaxf(fmaf(b1.y, s, h), 0.f);
            b1.z = fmaxf(fmaf(b1.z, s, h), 0.f); b1.w = fmaxf(fmaf(b1.w, s, h), 0.f);
        }
        __syncthreads();
        As[akq+0][ar] = dup2(a0.x); As[akq+1][ar] = dup2(a0.y);
        As[akq+2][ar] = dup2(a0.z); As[akq+3][ar] = dup2(a0.w);
        As[akq+4][ar] = dup2(a1.x); As[akq+5][ar] = dup2(a1.y);
        As[akq+6][ar] = dup2(a1.z); As[akq+7][ar] = dup2(a1.w);
        *(float4*)&Bs[bkr][bnc]     = b0;
        *(float4*)&Bs[bkr][bnc + 4] = b1;
        __syncthreads();
        #pragma unroll
        for (int kk = 0; kk < 16; ++kk) {
            unsigned long long af[8], bf[4];
            const unsigned long long* ap = &As[kk][ty*8];
            #pragma unroll
            for (int i = 0; i < 8; ++i) af[i] = ap[i];
            const unsigned long long* bp = (const unsigned long long*)&Bs[kk][tx*8];
            #pragma unroll
            for (int j = 0; j < 4; ++j) bf[j] = bp[j];
            #pragma unroll
            for (int i = 0; i < 8; ++i)
                #pragma unroll
                for (int j = 0; j < 4; ++j)
                    asm("fma.rn.f32x2 %0, %1, %2, %0;"
                        : "+l"(acc[i][j]) : "l"(af[i]), "l"(bf[j]));
        }
    }

    constexpr int ng5 = Nn >> 5;
    #pragma unroll
    for (int i = 0; i < 8; ++i) {
        int gr = m0 + ty*8 + i;
        float out[8];
        #pragma unroll
        for (int j = 0; j < 4; ++j) {
            out[2*j]   = __uint_as_float((unsigned int)(acc[i][j] & 0xffffffffull));
            out[2*j+1] = __uint_as_float((unsigned int)(acc[i][j] >> 32));
        }
        if (MODE == 1) {
            #pragma unroll
            for (int j = 0; j < 8; ++j)
                out[j] += g_h3[(size_t)gr*ng5 + ((n0 + tx*8 + j) >> 5)];
        }
        float4* cp = (float4*)(C + (size_t)gr*Nn + n0 + tx*8);
        cp[0] = make_float4(out[0], out[1], out[2], out[3]);
        cp[1] = make_float4(out[4], out[5], out[6], out[7]);
    }
}

// ---------------- final: out_feat = max_k relu(affine4(y4)) ------------------
__global__ void k_final(float* __restrict__ out) {
    int gid = blockIdx.x*256 + threadIdx.x;   // 256*4096
    int c = gid >> 12, bs = gid & 4095;
    int b = bs >> 10, s = bs & 1023;
    float sc = g_s4[c], h = g_t4[c];
    const float4* r = (const float4*)(g_y4 + (size_t)c*MTOT + bs*KNB);
    float mx = 0.f;
    #pragma unroll
    for (int j = 0; j < 8; ++j) {
        float4 v = r[j];
        mx = fmaxf(mx, fmaf(v.x, sc, h)); mx = fmaxf(mx, fmaf(v.y, sc, h));
        mx = fmaxf(mx, fmaf(v.z, sc, h)); mx = fmaxf(mx, fmaf(v.w, sc, h));
    }
    out[(((b << 8) + c) << 10) + s] = mx;
}

// ---------------- launcher ---------------------------------------------------
extern "C" void kernel_launch(void* const* d_in, const int* in_sizes, int n_in,
                              void* d_out, int out_size) {
    const float* p   = (const float*)d_in[0];
    const float* f   = (const float*)d_in[1];
    const float* w1  = (const float*)d_in[2];
    const float* w2  = (const float*)d_in[3];
    const float* b2  = (const float*)d_in[4];
    const float* g2  = (const float*)d_in[5];
    const float* be2 = (const float*)d_in[6];
    const float* w3  = (const float*)d_in[7];
    const float* g3  = (const float*)d_in[8];
    const float* be3 = (const float*)d_in[9];
    const float* w4  = (const float*)d_in[10];
    const float* g4  = (const float*)d_in[11];
    const float* be4 = (const float*)d_in[12];
    float* out = (float*)d_out;

    k_w21<<<1, 256>>>(w1, w2);
    k_fps<<<BB, 1024>>>(p, out);                      // writes cntrd into d_out[0..12288)
    k_knn<<<BB*NSAMP, 128>>>(p, out);
    k_gconv1<<<MTOT/256, 256>>>(p, f, b2);
    k_stats<2><<<256, 256>>>();
    k_params<2><<<2, 256>>>(g2, be2);
    k_xm<<<4096, 256>>>();
    k_gemm<0><<<dim3(4, (BB*NSAMP)/128), 256>>>(w3);        // h3 = w3a @ xm
    k_gemm<1><<<dim3(4, MTOT/128), 256>>>(w3 + 256);        // y3 = w3b @ x + h3
    k_stats<3><<<512, 256>>>();
    k_params<3><<<2, 256>>>(g3, be3);
    k_gemm<2><<<dim3(2, MTOT/128), 256>>>(w4);              // y4 = w4 @ x3
    k_stats<4><<<256, 256>>>();
    k_params<4><<<2, 256>>>(g4, be4);
    k_final<<<4096, 256>>>(out + BB*NSAMP*3);
}